// round 9
// baseline (speedup 1.0000x reference)
#include <cuda_runtime.h>
#include <cuda_bf16.h>
#include <cstdint>

#define T_FRAMES 16384
#define E_DIM    1024
#define M_MODELS 8
#define K_CLUST  512

#define TM   64             // frames per CTA
#define TN   256            // centroids per CTA (half the model)
#define KBLK 128            // fp8 K elements per stage (128B rows)
#define NSTAGE (E_DIM / KBLK)   // 8
#define MAXT (T_FRAMES / TM)    // 256
#define NTHREADS 512
#define TAU  20.0f
#define CAP  2048

// ---- persistent scratch ----
__device__ uint8_t g_cent_fp8[M_MODELS * K_CLUST * E_DIM];   // 4.2MB
__device__ uint8_t g_emb_fp8[T_FRAMES * E_DIM];              // 16.8MB
__device__ unsigned long long g_packed[T_FRAMES];
__device__ int   g_counts[M_MODELS];
__device__ int   g_rows[M_MODELS * T_FRAMES];
__device__ float g_chalf[M_MODELS * K_CLUST];

// ================= helpers =================
__device__ __forceinline__ uint32_t smem_u32(const void* p) {
    uint32_t a;
    asm("{ .reg .u64 t; cvta.to.shared.u64 t, %1; cvt.u32.u64 %0, t; }" : "=r"(a) : "l"(p));
    return a;
}
__device__ __forceinline__ void cp16(uint32_t dst, const void* src) {
    asm volatile("cp.async.cg.shared.global [%0], [%1], 16;" :: "r"(dst), "l"(src));
}
__device__ __forceinline__ void ldmx4(uint32_t addr, uint32_t& r0, uint32_t& r1,
                                      uint32_t& r2, uint32_t& r3) {
    asm volatile("ldmatrix.sync.aligned.m8n8.x4.shared.b16 {%0,%1,%2,%3}, [%4];"
                 : "=r"(r0), "=r"(r1), "=r"(r2), "=r"(r3) : "r"(addr));
}
__device__ __forceinline__ void mma_fp8(float* c, uint32_t a0, uint32_t a1,
                                        uint32_t a2, uint32_t a3,
                                        uint32_t b0, uint32_t b1) {
    asm volatile(
        "mma.sync.aligned.m16n8k32.row.col.f32.e4m3.e4m3.f32 "
        "{%0,%1,%2,%3}, {%4,%5,%6,%7}, {%8,%9}, {%0,%1,%2,%3};"
        : "+f"(c[0]), "+f"(c[1]), "+f"(c[2]), "+f"(c[3])
        : "r"(a0), "r"(a1), "r"(a2), "r"(a3), "r"(b0), "r"(b1));
}
__device__ __forceinline__ unsigned int fkey(float f) {
    unsigned u = __float_as_uint(f);
    return (u & 0x80000000u) ? ~u : (u | 0x80000000u);
}
// pack float4 -> 4 consecutive e4m3 bytes (x at lowest address)
__device__ __forceinline__ uint32_t f4_to_fp8(float4 v) {
    uint32_t p;
    asm("{ .reg .b16 lo, hi;\n\t"
        "cvt.rn.satfinite.e4m3x2.f32 lo, %2, %1;\n\t"
        "cvt.rn.satfinite.e4m3x2.f32 hi, %4, %3;\n\t"
        "mov.b32 %0, {lo, hi}; }"
        : "=r"(p) : "f"(v.x), "f"(v.y), "f"(v.z), "f"(v.w));
    return p;
}

// ================= smem layout (bytes) =================
#define SM_B      0                        // 2 x 32KB (256 rows x 128B)
#define SM_A      65536                    // 2 x 8KB  (64 rows x 128B)
#define SM_CHALF  81920                    // 256 f32
#define SM_ROWIDX 82944                    // 64 int
#define SM_THR    83200                    // 64 f32
#define SM_PMIN   83456                    // 64 x 4 f32
#define SM_CNT    84480                    // int (+pad)
#define SM_CAND   84496                    // CAP ints
#define SMEM_TOTAL (84496 + CAP * 4 + 16)  // ~92.7KB -> 2 CTAs/SM

// ================= prep kernels =================
__global__ void init_kernel() {
    int t = blockIdx.x * blockDim.x + threadIdx.x;
    if (t < T_FRAMES) g_packed[t] = 0xFFFFFFFFFFFFFFFFull;
    if (t < M_MODELS) g_counts[t] = 0;
}

__global__ void bucket_kernel(const int* __restrict__ model_idx) {
    int t = blockIdx.x * blockDim.x + threadIdx.x;
    if (t >= T_FRAMES) return;
    int m = model_idx[t];
    int pos = atomicAdd(&g_counts[m], 1);
    g_rows[m * T_FRAMES + pos] = t;
}

// one warp per centroid row: f32->e4m3 convert AND 0.5*|c|^2 in one read
__global__ void prep_cent_kernel(const float* __restrict__ cent) {
    int warp = (blockIdx.x * blockDim.x + threadIdx.x) >> 5;
    int lane = threadIdx.x & 31;
    if (warp >= M_MODELS * K_CLUST) return;
    const float4* src = reinterpret_cast<const float4*>(cent + (size_t)warp * E_DIM);
    uint32_t* dst = reinterpret_cast<uint32_t*>(g_cent_fp8 + (size_t)warp * E_DIM);
    float s = 0.f;
    #pragma unroll
    for (int q = 0; q < 8; ++q) {
        float4 v = src[lane + 32 * q];
        dst[lane + 32 * q] = f4_to_fp8(v);
        s += v.x * v.x + v.y * v.y + v.z * v.z + v.w * v.w;
    }
    #pragma unroll
    for (int o = 16; o; o >>= 1) s += __shfl_xor_sync(0xffffffffu, s, o);
    if (lane == 0) g_chalf[warp] = 0.5f * s;
}

// flat f32 -> e4m3 conversion of emb
__global__ void prep_emb_kernel(const float* __restrict__ emb) {
    int i = blockIdx.x * blockDim.x + threadIdx.x;   // float4 index
    if (i >= T_FRAMES * E_DIM / 4) return;
    float4 v = reinterpret_cast<const float4*>(emb)[i];
    reinterpret_cast<uint32_t*>(g_emb_fp8)[i] = f4_to_fp8(v);
}

// ================= fused GEMM + argmin + exact rescore =================
// grid.x = M_MODELS * MAXT : m = bx>>8, mt = bx&255 ; grid.y = nt (0..1)
__global__ __launch_bounds__(NTHREADS, 2)
void fused_kernel(const float* __restrict__ emb, const float* __restrict__ cent) {
    extern __shared__ char smem[];
    const uint32_t sb = smem_u32(smem);

    const int m  = blockIdx.x >> 8;
    const int mt = blockIdx.x & 255;
    const int cnt = g_counts[m];
    if (mt * TM >= cnt) return;
    const int nt = blockIdx.y;
    const int* rowsm = g_rows + m * T_FRAMES;

    const int tid  = threadIdx.x;
    const int wid  = tid >> 5;
    const int lane = tid & 31;
    const int wr = wid >> 2;      // 0..3 : 16-frame row group
    const int wc = wid & 3;       // 0..3 : 64-centroid col group

    int*   rowidx_s = reinterpret_cast<int*>(smem + SM_ROWIDX);
    float* chalf_s  = reinterpret_cast<float*>(smem + SM_CHALF);
    float* thr_s    = reinterpret_cast<float*>(smem + SM_THR);
    float* pmin_s   = reinterpret_cast<float*>(smem + SM_PMIN);
    int* cnt_s  = reinterpret_cast<int*>(smem + SM_CNT);
    int* cand_s = reinterpret_cast<int*>(smem + SM_CAND);

    if (tid < TM) {
        int gr = mt * TM + tid;
        rowidx_s[tid] = rowsm[min(gr, cnt - 1)];
    }
    if (tid < TN) chalf_s[tid] = g_chalf[m * K_CLUST + nt * TN + tid];
    if (tid == 0) cnt_s[0] = 0;
    __syncthreads();

    // ---- A producer plan (cp.async): 64 rows x 8 chunks = 512 = NTHREADS ----
    const int ar = tid >> 3, ac = tid & 7;
    const char* aS = reinterpret_cast<const char*>(
        g_emb_fp8 + (size_t)rowidx_s[ar] * E_DIM) + ac * 16;
    const uint32_t ad = ar * 128 + ((ac ^ (ar & 7)) << 4);

    // ---- B producer plan: half-row per thread (4 x 16B chunks/stage) ----
    const int brow = tid >> 1, bh = tid & 1;
    const char* bS = reinterpret_cast<const char*>(
        g_cent_fp8 + ((size_t)m * K_CLUST + nt * TN + brow) * E_DIM) + bh * 64;
    uint32_t bd[4];
    #pragma unroll
    for (int c = 0; c < 4; ++c)
        bd[c] = brow * 128 + (((bh * 4 + c) ^ (brow & 7)) << 4);

    float acc[8][4];
    #pragma unroll
    for (int n = 0; n < 8; ++n)
        #pragma unroll
        for (int r = 0; r < 4; ++r) acc[n][r] = 0.f;

    const int arow_l = wr * 16 + (lane & 7) + ((lane >> 3) & 1) * 8;
    const int brow_l = wc * 64 + (lane & 7) + ((lane >> 3) & 1) * 8;
    const int clane  = lane >> 4;

    // prologue: stage 0 (A + B in one group)
    cp16(sb + SM_A + ad, aS);
    #pragma unroll
    for (int c = 0; c < 4; ++c) cp16(sb + SM_B + bd[c], bS + c * 16);
    asm volatile("cp.async.commit_group;" ::: "memory");

    for (int kb = 0; kb < NSTAGE; ++kb) {
        const uint32_t Ab = sb + SM_A + (kb & 1) * 8192;
        const uint32_t Bb = sb + SM_B + (kb & 1) * 32768;
        if (kb + 1 < NSTAGE) {
            uint32_t An = sb + SM_A + ((kb + 1) & 1) * 8192;
            uint32_t Bn = sb + SM_B + ((kb + 1) & 1) * 32768;
            cp16(An + ad, aS + (kb + 1) * 128);
            #pragma unroll
            for (int c = 0; c < 4; ++c) cp16(Bn + bd[c], bS + (kb + 1) * 128 + c * 16);
            asm volatile("cp.async.commit_group;" ::: "memory");
            asm volatile("cp.async.wait_group 1;" ::: "memory");
        } else {
            asm volatile("cp.async.wait_group 0;" ::: "memory");
        }
        __syncthreads();

        #pragma unroll
        for (int ks = 0; ks < 4; ++ks) {          // k32 slice within the 128-fp8 stage
            const int cc = ks * 2 + clane;
            uint32_t a0, a1, a2, a3;
            ldmx4(Ab + arow_l * 128 + ((cc ^ (arow_l & 7)) << 4), a0, a1, a2, a3);
            #pragma unroll
            for (int nh = 0; nh < 2; ++nh) {
                uint32_t b[2][4];
                #pragma unroll
                for (int nj = 0; nj < 2; ++nj) {
                    int row = brow_l + nh * 32 + nj * 16;
                    ldmx4(Bb + row * 128 + ((cc ^ (row & 7)) << 4),
                          b[nj][0], b[nj][1], b[nj][2], b[nj][3]);
                }
                #pragma unroll
                for (int n = 0; n < 4; ++n)
                    mma_fp8(acc[nh * 4 + n], a0, a1, a2, a3,
                            b[n >> 1][n & 1], b[n >> 1][2 + (n & 1)]);
            }
        }
        __syncthreads();
    }

    // ---- epilogue 1: per-row approx min over this warp's 64 cols ----
    const int gid = lane >> 2, tig = lane & 3;
    {
        float v0 = __int_as_float(0x7F800000), v1 = v0;
        #pragma unroll
        for (int n = 0; n < 8; ++n) {
            int col = wc * 64 + n * 8 + tig * 2;
            float c0 = chalf_s[col], c1 = chalf_s[col + 1];
            v0 = fminf(v0, fminf(c0 - acc[n][0], c1 - acc[n][1]));
            v1 = fminf(v1, fminf(c0 - acc[n][2], c1 - acc[n][3]));
        }
        #pragma unroll
        for (int o = 1; o < 4; o <<= 1) {
            v0 = fminf(v0, __shfl_xor_sync(0xffffffffu, v0, o));
            v1 = fminf(v1, __shfl_xor_sync(0xffffffffu, v1, o));
        }
        if (tig == 0) {
            pmin_s[(wr * 16 + gid) * 4 + wc] = v0;
            pmin_s[(wr * 16 + gid + 8) * 4 + wc] = v1;
        }
    }
    __syncthreads();
    if (tid < TM) {
        float v = pmin_s[tid * 4];
        #pragma unroll
        for (int w = 1; w < 4; ++w) v = fminf(v, pmin_s[tid * 4 + w]);
        thr_s[tid] = v + TAU;     // half-local threshold: superset of global-thr set
    }
    __syncthreads();

    // ---- epilogue 2: collect candidates (cols local to this half) ----
    #pragma unroll
    for (int n = 0; n < 8; ++n) {
        #pragma unroll
        for (int r = 0; r < 4; ++r) {
            int row = wr * 16 + gid + (r >> 1) * 8;
            int col = wc * 64 + n * 8 + tig * 2 + (r & 1);
            float s = chalf_s[col] - acc[n][r];
            if (s <= thr_s[row]) {
                int idx = atomicAdd(cnt_s, 1);
                if (idx < CAP) cand_s[idx] = (row << 16) | col;
            }
        }
    }
    __syncthreads();
    const int ncand = min(cnt_s[0], CAP);

    // ---- epilogue 3: exact fp32 rescore; merge across CTAs via atomicMin ----
    const float4* emb4  = reinterpret_cast<const float4*>(emb);
    const float4* cent4 = reinterpret_cast<const float4*>(cent);
    for (int i = wid; i < ncand; i += 16) {
        int rc = cand_s[i];
        int row = rc >> 16, col = rc & 0xFFFF;
        const float4* e4 = emb4 + (size_t)rowidx_s[row] * 256;
        const float4* c4 = cent4 + ((size_t)m * K_CLUST + nt * TN + col) * 256;
        float d = 0.f;
        #pragma unroll
        for (int q = 0; q < 8; ++q) {
            float4 ea = e4[q * 32 + lane];
            float4 ca = c4[q * 32 + lane];
            d += ea.x * ca.x + ea.y * ca.y + ea.z * ca.z + ea.w * ca.w;
        }
        #pragma unroll
        for (int o = 16; o; o >>= 1) d += __shfl_xor_sync(0xffffffffu, d, o);
        if (lane == 0 && (mt * TM + row) < cnt) {
            float s = chalf_s[col] - d;   // exact fp32 score
            unsigned long long key =
                ((unsigned long long)fkey(s) << 32) | (unsigned)(nt * TN + col);
            atomicMin(&g_packed[rowidx_s[row]], key);  // exact: order-independent
        }
    }
}

// ================= output gather =================
__global__ void gather_kernel(const float* __restrict__ cent,
                              const int* __restrict__ model_idx,
                              float* __restrict__ out) {
    int idx = blockIdx.x * blockDim.x + threadIdx.x;   // float4 index
    if (idx >= T_FRAMES * (E_DIM / 4)) return;
    int t  = idx >> 8;
    int e4 = idx & 255;
    int code = (int)(unsigned)(g_packed[t] & 0xFFFFFFFFull);
    size_t row = (size_t)(model_idx[t] * K_CLUST + code);
    reinterpret_cast<float4*>(out)[idx] =
        reinterpret_cast<const float4*>(cent)[row * 256 + e4];
}

// ================= launch =================
extern "C" void kernel_launch(void* const* d_in, const int* in_sizes, int n_in,
                              void* d_out, int out_size) {
    const float* emb  = (const float*)d_in[0];
    const float* cent = (const float*)d_in[1];
    const int*   midx = (const int*)d_in[2];
    float* out = (float*)d_out;

    cudaFuncSetAttribute(fused_kernel,
                         cudaFuncAttributeMaxDynamicSharedMemorySize, SMEM_TOTAL);

    init_kernel<<<(T_FRAMES + 255) / 256, 256>>>();
    bucket_kernel<<<(T_FRAMES + 255) / 256, 256>>>(midx);
    prep_cent_kernel<<<(M_MODELS * K_CLUST * 32 + 255) / 256, 256>>>(cent);
    prep_emb_kernel<<<(T_FRAMES * E_DIM / 4 + 255) / 256, 256>>>(emb);

    dim3 grid(M_MODELS * MAXT, 2);   // (2048, 2); empty m-tiles exit early
    fused_kernel<<<grid, NTHREADS, SMEM_TOTAL>>>(emb, cent);

    gather_kernel<<<(T_FRAMES * (E_DIM / 4) + 255) / 256, 256>>>(cent, midx, out);
}

// round 10
// speedup vs baseline: 1.3384x; 1.3384x over previous
#include <cuda_runtime.h>
#include <cuda_bf16.h>
#include <cstdint>

#define T_FRAMES 16384
#define E_DIM    1024
#define M_MODELS 8
#define K_CLUST  512

#define TM   64             // frames per CTA tile
#define TN   512            // all centroids of the model
#define KBLK 128            // fp8 K elements per stage (128B rows)
#define NSTAGE (E_DIM / KBLK)   // 8
#define MAXT_G 40           // grid tiles per model (tile-stride loop guards overflow)
#define NTHREADS 1024
#define TAU  20.0f
#define CAP  4096

#define B_STAGE_BYTES (K_CLUST * KBLK)          // 64KB

// ---- persistent scratch ----
// stage-major, pre-swizzled: [m][stage][row][128B]
__device__ uint8_t g_cent_s8[M_MODELS * NSTAGE * B_STAGE_BYTES];   // 4.2MB
__device__ int   g_counts[M_MODELS];
__device__ int   g_rows[M_MODELS * T_FRAMES];
__device__ float g_chalf[M_MODELS * K_CLUST];

// ================= helpers =================
__device__ __forceinline__ uint32_t smem_u32(const void* p) {
    uint32_t a;
    asm("{ .reg .u64 t; cvta.to.shared.u64 t, %1; cvt.u32.u64 %0, t; }" : "=r"(a) : "l"(p));
    return a;
}
__device__ __forceinline__ void bulk_g2s(uint32_t dst, const void* src,
                                         uint32_t bytes, uint32_t mbar) {
    asm volatile(
        "cp.async.bulk.shared::cluster.global.mbarrier::complete_tx::bytes [%0], [%1], %2, [%3];"
        :: "r"(dst), "l"(src), "r"(bytes), "r"(mbar) : "memory");
}
#define MBARRIER_INIT(addr, cnt) \
    asm volatile("mbarrier.init.shared.b64 [%0], %1;" :: "r"((uint32_t)(addr)), "r"((uint32_t)(cnt)) : "memory")
#define MBARRIER_EXPECT_TX(addr, bytes) \
    asm volatile("mbarrier.arrive.expect_tx.shared.b64 _, [%0], %1;" \
                 :: "r"((uint32_t)(addr)), "r"((uint32_t)(bytes)) : "memory")
#define MBARRIER_WAIT_PARITY(addr, par) do { \
    uint32_t _mb = (uint32_t)(addr); uint32_t _pr = (uint32_t)(par); uint32_t _done; \
    asm volatile("{\n\t.reg .pred p;\n\t" \
        "mbarrier.try_wait.parity.acquire.cta.shared::cta.b64 p, [%1], %2;\n\t" \
        "selp.b32 %0, 1, 0, p;\n\t}" : "=r"(_done) : "r"(_mb), "r"(_pr) : "memory"); \
    if (!_done) { \
        asm volatile("{\n\t.reg .pred P1;\n\t" \
            "WL_%=:\n\t" \
            "mbarrier.try_wait.parity.acquire.cta.shared::cta.b64 P1, [%0], %1, 0x989680;\n\t" \
            "@P1 bra.uni WD_%=;\n\t" \
            "bra.uni WL_%=;\n\t" \
            "WD_%=:\n\t}" :: "r"(_mb), "r"(_pr) : "memory"); \
    } } while (0)
__device__ __forceinline__ void ldmx4(uint32_t addr, uint32_t& r0, uint32_t& r1,
                                      uint32_t& r2, uint32_t& r3) {
    asm volatile("ldmatrix.sync.aligned.m8n8.x4.shared.b16 {%0,%1,%2,%3}, [%4];"
                 : "=r"(r0), "=r"(r1), "=r"(r2), "=r"(r3) : "r"(addr));
}
__device__ __forceinline__ void mma_fp8(float* c, uint32_t a0, uint32_t a1,
                                        uint32_t a2, uint32_t a3,
                                        uint32_t b0, uint32_t b1) {
    asm volatile(
        "mma.sync.aligned.m16n8k32.row.col.f32.e4m3.e4m3.f32 "
        "{%0,%1,%2,%3}, {%4,%5,%6,%7}, {%8,%9}, {%0,%1,%2,%3};"
        : "+f"(c[0]), "+f"(c[1]), "+f"(c[2]), "+f"(c[3])
        : "r"(a0), "r"(a1), "r"(a2), "r"(a3), "r"(b0), "r"(b1));
}
__device__ __forceinline__ unsigned int fkey(float f) {
    unsigned u = __float_as_uint(f);
    return (u & 0x80000000u) ? ~u : (u | 0x80000000u);
}
__device__ __forceinline__ uint32_t f4_to_fp8(float4 v) {
    uint32_t p;
    asm("{ .reg .b16 lo, hi;\n\t"
        "cvt.rn.satfinite.e4m3x2.f32 lo, %2, %1;\n\t"
        "cvt.rn.satfinite.e4m3x2.f32 hi, %4, %3;\n\t"
        "mov.b32 %0, {lo, hi}; }"
        : "=r"(p) : "f"(v.x), "f"(v.y), "f"(v.z), "f"(v.w));
    return p;
}

// ================= smem layout (bytes) =================
#define SM_B      0                        // 2 x 64KB
#define SM_A      131072                   // 2 x 8KB
#define SM_CHALF  147456                   // 512 f32
#define SM_ROWIDX 149504                   // 64 int
#define SM_THR    149760                   // 64 f32
#define SM_PMIN   150016                   // 64 x 8 f32
#define SM_BEST   152064                   // 64 u64
#define SM_MBAR   152576                   // 2 x 8B
#define SM_CNT    152592                   // int (+pad)
#define SM_CODE   152608                   // 64 int
#define SM_CAND   152864                   // CAP ints
#define SMEM_TOTAL (152864 + CAP * 4 + 32) // ~166KB -> 1 CTA/SM

// ================= prep kernels =================
__global__ void init_kernel() {
    int t = threadIdx.x;
    if (t < M_MODELS) g_counts[t] = 0;
}

__global__ void bucket_kernel(const int* __restrict__ model_idx) {
    int t = blockIdx.x * blockDim.x + threadIdx.x;
    if (t >= T_FRAMES) return;
    int m = model_idx[t];
    int pos = atomicAdd(&g_counts[m], 1);
    g_rows[m * T_FRAMES + pos] = t;
}

// one warp per centroid row: f32 -> e4m3 into stage-major pre-swizzled layout,
// plus 0.5*|c|^2, in a single read of cent.
__global__ void prep_cent_kernel(const float* __restrict__ cent) {
    int warp = (blockIdx.x * blockDim.x + threadIdx.x) >> 5;   // global centroid row
    int lane = threadIdx.x & 31;
    if (warp >= M_MODELS * K_CLUST) return;
    const int m = warp >> 9;            // /512
    const int r = warp & 511;           // row within model == smem row
    const float4* src = reinterpret_cast<const float4*>(cent + (size_t)warp * E_DIM);
    uint8_t* base = g_cent_s8 + (size_t)m * NSTAGE * B_STAGE_BYTES;
    const uint32_t sw16 = ((lane >> 2) ^ (r & 7)) << 4;   // swizzled 16B chunk
    const uint32_t boff = (lane & 3) * 4;
    float s = 0.f;
    #pragma unroll
    for (int q = 0; q < 8; ++q) {      // q == stage
        float4 v = src[lane + 32 * q];
        *reinterpret_cast<uint32_t*>(base + q * B_STAGE_BYTES + r * 128 + sw16 + boff)
            = f4_to_fp8(v);
        s += v.x * v.x + v.y * v.y + v.z * v.z + v.w * v.w;
    }
    #pragma unroll
    for (int o = 16; o; o >>= 1) s += __shfl_xor_sync(0xffffffffu, s, o);
    if (lane == 0) g_chalf[warp] = 0.5f * s;
}

// ================= fused GEMM + argmin + rescore + output =================
// grid.x = M_MODELS * MAXT_G : m = bx / MAXT_G, tile-stride loop over mt
__global__ __launch_bounds__(NTHREADS, 1)
void fused_kernel(const float* __restrict__ emb, const float* __restrict__ cent,
                  float* __restrict__ out) {
    extern __shared__ char smem[];
    const uint32_t sb = smem_u32(smem);

    const int m   = blockIdx.x / MAXT_G;
    const int mtb = blockIdx.x % MAXT_G;
    const int cnt = g_counts[m];
    const int ntiles = (cnt + TM - 1) / TM;
    const int* rowsm = g_rows + m * T_FRAMES;

    const int tid  = threadIdx.x;
    const int wid  = tid >> 5;
    const int lane = tid & 31;
    const int wr = wid >> 3;      // 0..3 : 16-frame row group
    const int wc = wid & 7;       // 0..7 : 64-centroid col group

    int*   rowidx_s = reinterpret_cast<int*>(smem + SM_ROWIDX);
    float* chalf_s  = reinterpret_cast<float*>(smem + SM_CHALF);
    float* thr_s    = reinterpret_cast<float*>(smem + SM_THR);
    float* pmin_s   = reinterpret_cast<float*>(smem + SM_PMIN);
    unsigned long long* best_s = reinterpret_cast<unsigned long long*>(smem + SM_BEST);
    int* cnt_s  = reinterpret_cast<int*>(smem + SM_CNT);
    int* code_s = reinterpret_cast<int*>(smem + SM_CODE);
    int* cand_s = reinterpret_cast<int*>(smem + SM_CAND);

    if (tid < TN) chalf_s[tid] = g_chalf[m * K_CLUST + tid];
    if (tid == 0) {
        MBARRIER_INIT(sb + SM_MBAR, 1);
        MBARRIER_INIT(sb + SM_MBAR + 8, 1);
    }
    __syncthreads();

    const uint8_t* bsrc = g_cent_s8 + (size_t)m * NSTAGE * B_STAGE_BYTES;
    const float4* emb4  = reinterpret_cast<const float4*>(emb);
    const float4* cent4 = reinterpret_cast<const float4*>(cent);

    const int ar = tid >> 4, af = tid & 15;   // A: row 0..63, 8-float slot 0..15
    const uint32_t ad = ar * 128 + (((af >> 1) ^ (ar & 7)) << 4) + (af & 1) * 8;
    const int arow_l = wr * 16 + (lane & 7) + ((lane >> 3) & 1) * 8;
    const int brow_l = wc * 64 + (lane & 7) + ((lane >> 3) & 1) * 8;
    const int clane  = lane >> 4;
    const int gid = lane >> 2, tig = lane & 3;

    uint32_t par[2] = {0, 0};

    for (int mt = mtb; mt < ntiles; mt += MAXT_G) {
        __syncthreads();   // previous tile's epilogue readers done before rowidx overwrite
        if (tid < TM) {
            int gr = mt * TM + tid;
            rowidx_s[tid] = rowsm[min(gr, cnt - 1)];
            best_s[tid] = 0xFFFFFFFFFFFFFFFFull;
        }
        if (tid == 0) cnt_s[0] = 0;
        __syncthreads();

        const float4* aS = emb4 + (size_t)rowidx_s[ar] * 256 + af * 2;

        float acc[8][4];
        #pragma unroll
        for (int n = 0; n < 8; ++n)
            #pragma unroll
            for (int r = 0; r < 4; ++r) acc[n][r] = 0.f;

        // prologue: stage 0 B bulk + stage 0 A regs
        if (tid == 0) {
            MBARRIER_EXPECT_TX(sb + SM_MBAR, B_STAGE_BYTES);
            bulk_g2s(sb + SM_B, bsrc, B_STAGE_BYTES, sb + SM_MBAR);
        }
        float4 apre0 = aS[0], apre1 = aS[1];

        for (int kb = 0; kb < NSTAGE; ++kb) {
            const int buf = kb & 1;
            const uint32_t Ab = sb + SM_A + buf * 8192;
            const uint32_t Bb = sb + SM_B + buf * 65536;
            // store current A stage (fp8-converted)
            *reinterpret_cast<uint2*>(smem + SM_A + buf * 8192 + ad) =
                make_uint2(f4_to_fp8(apre0), f4_to_fp8(apre1));
            // issue next B bulk + prefetch next A
            if (kb + 1 < NSTAGE) {
                const int nb = (kb + 1) & 1;
                if (tid == 0) {
                    MBARRIER_EXPECT_TX(sb + SM_MBAR + 8 * nb, B_STAGE_BYTES);
                    bulk_g2s(sb + SM_B + nb * 65536, bsrc + (kb + 1) * B_STAGE_BYTES,
                             B_STAGE_BYTES, sb + SM_MBAR + 8 * nb);
                }
                apre0 = aS[(kb + 1) * 32];
                apre1 = aS[(kb + 1) * 32 + 1];
            }
            // wait current B, make A visible
            MBARRIER_WAIT_PARITY(sb + SM_MBAR + 8 * buf, par[buf]);
            par[buf] ^= 1;
            __syncthreads();

            #pragma unroll
            for (int ks = 0; ks < 4; ++ks) {      // k32 slice within 128-fp8 stage
                const int cc = ks * 2 + clane;
                uint32_t a0, a1, a2, a3;
                ldmx4(Ab + arow_l * 128 + ((cc ^ (arow_l & 7)) << 4), a0, a1, a2, a3);
                #pragma unroll
                for (int nh = 0; nh < 2; ++nh) {
                    uint32_t b[2][4];
                    #pragma unroll
                    for (int nj = 0; nj < 2; ++nj) {
                        int row = brow_l + nh * 32 + nj * 16;
                        ldmx4(Bb + row * 128 + ((cc ^ (row & 7)) << 4),
                              b[nj][0], b[nj][1], b[nj][2], b[nj][3]);
                    }
                    #pragma unroll
                    for (int n = 0; n < 4; ++n)
                        mma_fp8(acc[nh * 4 + n], a0, a1, a2, a3,
                                b[n >> 1][n & 1], b[n >> 1][2 + (n & 1)]);
                }
            }
            __syncthreads();   // all reads of this buffer done before its reuse
        }

        // ---- epilogue 1: per-row approx min over this warp's 64 cols ----
        {
            float v0 = __int_as_float(0x7F800000), v1 = v0;
            #pragma unroll
            for (int n = 0; n < 8; ++n) {
                int col = wc * 64 + n * 8 + tig * 2;
                float c0 = chalf_s[col], c1 = chalf_s[col + 1];
                v0 = fminf(v0, fminf(c0 - acc[n][0], c1 - acc[n][1]));
                v1 = fminf(v1, fminf(c0 - acc[n][2], c1 - acc[n][3]));
            }
            #pragma unroll
            for (int o = 1; o < 4; o <<= 1) {
                v0 = fminf(v0, __shfl_xor_sync(0xffffffffu, v0, o));
                v1 = fminf(v1, __shfl_xor_sync(0xffffffffu, v1, o));
            }
            if (tig == 0) {
                pmin_s[(wr * 16 + gid) * 8 + wc] = v0;
                pmin_s[(wr * 16 + gid + 8) * 8 + wc] = v1;
            }
        }
        __syncthreads();
        if (tid < TM) {
            float v = pmin_s[tid * 8];
            #pragma unroll
            for (int w = 1; w < 8; ++w) v = fminf(v, pmin_s[tid * 8 + w]);
            thr_s[tid] = v + TAU;
        }
        __syncthreads();

        // ---- epilogue 2: collect candidates ----
        #pragma unroll
        for (int n = 0; n < 8; ++n) {
            #pragma unroll
            for (int r = 0; r < 4; ++r) {
                int row = wr * 16 + gid + (r >> 1) * 8;
                int col = wc * 64 + n * 8 + tig * 2 + (r & 1);
                float s = chalf_s[col] - acc[n][r];
                if (s <= thr_s[row]) {
                    int idx = atomicAdd(cnt_s, 1);
                    if (idx < CAP) cand_s[idx] = (row << 16) | col;
                }
            }
        }
        __syncthreads();
        const int ncand = min(cnt_s[0], CAP);

        // ---- epilogue 3: exact fp32 rescore (one warp per candidate) ----
        for (int i = wid; i < ncand; i += 32) {
            int rc = cand_s[i];
            int row = rc >> 16, col = rc & 0xFFFF;
            const float4* e4 = emb4 + (size_t)rowidx_s[row] * 256;
            const float4* c4 = cent4 + ((size_t)m * K_CLUST + col) * 256;
            float d = 0.f;
            #pragma unroll
            for (int q = 0; q < 8; ++q) {
                float4 ea = e4[q * 32 + lane];
                float4 ca = c4[q * 32 + lane];
                d += ea.x * ca.x + ea.y * ca.y + ea.z * ca.z + ea.w * ca.w;
            }
            #pragma unroll
            for (int o = 16; o; o >>= 1) d += __shfl_xor_sync(0xffffffffu, d, o);
            if (lane == 0) {
                float s = chalf_s[col] - d;   // exact fp32 score
                unsigned long long key = ((unsigned long long)fkey(s) << 32) | (unsigned)col;
                atomicMin(&best_s[row], key); // ties -> smaller col (first-min)
            }
        }
        __syncthreads();
        if (tid < TM) code_s[tid] = (int)(unsigned)(best_s[tid] & 0xFFFFFFFFull);
        __syncthreads();

        // ---- epilogue 4: write output rows directly ----
        float4* out4 = reinterpret_cast<float4*>(out);
        for (int idx = tid; idx < TM * 256; idx += NTHREADS) {
            int r = idx >> 8, q = idx & 255;
            if (mt * TM + r < cnt) {
                int frame = rowidx_s[r];
                out4[(size_t)frame * 256 + q] =
                    cent4[((size_t)m * K_CLUST + code_s[r]) * 256 + q];
            }
        }
    }
}

// ================= launch =================
extern "C" void kernel_launch(void* const* d_in, const int* in_sizes, int n_in,
                              void* d_out, int out_size) {
    const float* emb  = (const float*)d_in[0];
    const float* cent = (const float*)d_in[1];
    const int*   midx = (const int*)d_in[2];
    float* out = (float*)d_out;

    cudaFuncSetAttribute(fused_kernel,
                         cudaFuncAttributeMaxDynamicSharedMemorySize, SMEM_TOTAL);

    init_kernel<<<1, 32>>>();
    bucket_kernel<<<(T_FRAMES + 255) / 256, 256>>>(midx);
    prep_cent_kernel<<<(M_MODELS * K_CLUST * 32 + 255) / 256, 256>>>(cent);

    fused_kernel<<<M_MODELS * MAXT_G, NTHREADS, SMEM_TOTAL>>>(emb, cent, out);
}